// round 15
// baseline (speedup 1.0000x reference)
#include <cuda_runtime.h>

#define NB 8
#define NN 512
#define DD 256
#define DH 64
#define OUT_ELEMS (NB*NN*DH)            // 262144
#define E4        16777216u             // e element count / 4

// region B: pre-copied by attention blocks before their QKV spin (R13 proven)
#define B_F4      1048576u              // 256 blk * 256 thr * 16 f4  (16 MB)
#define E4A       (E4 - B_F4)           // 15728640 = 15360 * 1024 exactly
#define SB        65536u                // stride: 256 blk * 256 thr

#define NBLK_QKV 192
#define NBLK_ATT 256
#define NBLK_CPY 1536
#define GRID     (NBLK_QKV + NBLK_ATT + NBLK_CPY)   // 1984
#define CPY_BLKS 1728u                  // copy-capable blocks (QKV + pure)

#define TMA_CHUNK_F4 1024u              // 16 KB per bulk chunk
#define TMA_CHUNKS   15360u             // E4A / TMA_CHUNK_F4
#define TMA_BYTES    16384u

__device__ float g_Q[NB*NN*DH];
__device__ float g_K[NB*NN*DH];
__device__ float g_V[NB*NN*DH];
__device__ unsigned g_qkv_done = 0;
__device__ unsigned g_att_done = 0;

// ---------------------------------------------------------------------------
// TMA bulk copy: global -> smem -> global, double-buffered, thread 0 only.
// Entirely bypasses the LSU/L1tex register path.
// ---------------------------------------------------------------------------
__device__ __forceinline__ void do_copy_tma(int t, unsigned lane,
                                            const float4* __restrict__ e4,
                                            float4* __restrict__ eo4,
                                            void* smbuf)
{
    if (t != 0) return;                 // other 255 threads retire immediately
    unsigned sb  = (unsigned)__cvta_generic_to_shared(smbuf);
    unsigned mb0 = sb + 2u * TMA_BYTES;
    unsigned mb1 = mb0 + 8u;
    asm volatile("mbarrier.init.shared.b64 [%0], 1;" :: "r"(mb0) : "memory");
    asm volatile("mbarrier.init.shared.b64 [%0], 1;" :: "r"(mb1) : "memory");
    asm volatile("fence.proxy.async.shared::cta;" ::: "memory");

    int ph0 = 0, ph1 = 0;
    #pragma unroll 1
    for (unsigned i = 0; ; i++) {
        unsigned chunk = lane + i * CPY_BLKS;
        if (chunk >= TMA_CHUNKS) break;
        unsigned bi  = i & 1u;
        unsigned buf = sb + bi * TMA_BYTES;
        unsigned mb  = bi ? mb1 : mb0;
        int      ph  = bi ? ph1 : ph0;

        // buffer reuse guard: at most 1 outstanding store group
        if (i >= 2)
            asm volatile("cp.async.bulk.wait_group 1;" ::: "memory");

        const void* src = (const void*)(e4  + (size_t)chunk * TMA_CHUNK_F4);
        void*       dst = (void*)      (eo4 + (size_t)chunk * TMA_CHUNK_F4);

        asm volatile("mbarrier.arrive.expect_tx.shared.b64 _, [%0], %1;"
                     :: "r"(mb), "r"(TMA_BYTES) : "memory");
        asm volatile("cp.async.bulk.shared::cluster.global.mbarrier::complete_tx::bytes "
                     "[%0], [%1], %2, [%3];"
                     :: "r"(buf), "l"(src), "r"(TMA_BYTES), "r"(mb) : "memory");

        // wait for the load to land (parity)
        unsigned done;
        do {
            asm volatile("{\n\t.reg .pred p;\n\t"
                         "mbarrier.try_wait.parity.shared.b64 p, [%1], %2, 0x989680;\n\t"
                         "selp.b32 %0, 1, 0, p;\n\t}"
                         : "=r"(done) : "r"(mb), "r"((unsigned)ph) : "memory");
        } while (!done);
        if (bi) ph1 ^= 1; else ph0 ^= 1;

        asm volatile("cp.async.bulk.global.shared::cta.bulk_group [%0], [%1], %2;"
                     :: "l"(dst), "r"(buf), "r"(TMA_BYTES) : "memory");
        asm volatile("cp.async.bulk.commit_group;" ::: "memory");
    }
    asm volatile("cp.async.bulk.wait_group 0;" ::: "memory");
}

__global__ void __launch_bounds__(256, 4) fused_kernel(
    const float* __restrict__ x, const int* __restrict__ mask,
    const float* __restrict__ Wq, const float* __restrict__ bq,
    const float* __restrict__ Wk, const float* __restrict__ bk,
    const float* __restrict__ Wv, const float* __restrict__ bv,
    const float4* __restrict__ e4, float4* __restrict__ eo4,
    float* __restrict__ outp)
{
    __shared__ __align__(128) char sm_raw[42688];
    int t = threadIdx.x;
    unsigned bid = blockIdx.x;

    if (bid < NBLK_QKV) {
        // =================== QKV GEMM role ===================
        float* Xs = (float*)sm_raw;          // 64*65
        float* Ws = Xs + 64*65;              // 64*64

        int which  = bid / 64;               // 0=Q, 1=K, 2=V
        int rowblk = bid % 64;
        const float* W    = (which == 0) ? Wq : (which == 1) ? Wk : Wv;
        const float* bias = (which == 0) ? bq : (which == 1) ? bk : bv;
        float* outw       = (which == 0) ? g_Q : (which == 1) ? g_K : g_V;

        int tx = t & 15;
        int ty = t >> 4;
        int row0 = rowblk * 64;

        float acc[4][4];
        #pragma unroll
        for (int i = 0; i < 4; i++)
            #pragma unroll
            for (int j = 0; j < 4; j++) acc[i][j] = 0.f;

        for (int kt = 0; kt < 4; kt++) {
            int k0 = kt * 64;
            __syncthreads();
            #pragma unroll
            for (int idx = t; idx < 4096; idx += 256) {
                int r  = idx >> 6;
                int kk = idx & 63;
                Xs[r * 65 + kk] = x[(row0 + r) * DD + k0 + kk];
                Ws[idx]         = W[k0 * DH + idx];
            }
            __syncthreads();

            const float4* Ws4 = (const float4*)Ws;
            #pragma unroll 8
            for (int kk = 0; kk < 64; kk++) {
                float4 bv4 = Ws4[kk * 16 + tx];
                #pragma unroll
                for (int i = 0; i < 4; i++) {
                    float a = Xs[(ty * 4 + i) * 65 + kk];
                    acc[i][0] += a * bv4.x;
                    acc[i][1] += a * bv4.y;
                    acc[i][2] += a * bv4.z;
                    acc[i][3] += a * bv4.w;
                }
            }
        }

        #pragma unroll
        for (int i = 0; i < 4; i++) {
            int r = row0 + ty * 4 + i;
            float m = (float)mask[r];
            float4 o;
            o.x = (acc[i][0] + bias[tx * 4 + 0]) * m;
            o.y = (acc[i][1] + bias[tx * 4 + 1]) * m;
            o.z = (acc[i][2] + bias[tx * 4 + 2]) * m;
            o.w = (acc[i][3] + bias[tx * 4 + 3]) * m;
            *(float4*)(outw + r * DH + tx * 4) = o;
        }

        __threadfence();
        __syncthreads();                 // all warps done with Xs/Ws before t0 reuses smem
        if (t == 0) atomicAdd(&g_qkv_done, 1u);

        do_copy_tma(t, bid, e4, eo4, sm_raw);
        return;
    }

    if (bid >= NBLK_QKV + NBLK_ATT) {
        // =================== pure copy role ===================
        do_copy_tma(t, bid - NBLK_ATT, e4, eo4, sm_raw);
        return;
    }

    // =================== attention role ===================
    // Pre-copy region B while the QKV GEMMs run (R13 proven).
    {
        unsigned cid = bid - NBLK_QKV;
        unsigned g = E4A + cid * 256u + (unsigned)t;
        #pragma unroll 1
        for (int it = 0; it < 4; it++) {
            unsigned i = g + (unsigned)it * 4u * SB;
            float4 a = __ldcs(e4 + i);
            float4 b = __ldcs(e4 + i + SB);
            float4 c = __ldcs(e4 + i + 2u*SB);
            float4 d = __ldcs(e4 + i + 3u*SB);
            __stcs(eo4 + i,         a);
            __stcs(eo4 + i + SB,    b);
            __stcs(eo4 + i + 2u*SB, c);
            __stcs(eo4 + i + 3u*SB, d);
        }
    }

    if (t == 0) {
        while (atomicAdd(&g_qkv_done, 0u) < (unsigned)NBLK_QKV)
            __nanosleep(64);
    }
    __syncthreads();
    __threadfence();

    float* Qs     = (float*)sm_raw;      // 16*64 = 1024
    float* Ks     = Qs + 1024;           // 64*68 = 4352 (later: reduction scratch)
    float* Vs     = Ks + 4352;           // 64*64 = 4096
    float* Ss     = Vs + 4096;           // 16*68 = 1088 (P, padded stride 68)
    float* coef_s = Ss + 1088;           // 16
    float* l_s    = coef_s + 16;         // 16
    int*   mj_s   = (int*)(l_s + 16);    // 64
    int*   mi_s   = mj_s + 64;           // 16

    int blk = bid - NBLK_QKV;
    int b   = blk >> 5;
    int i0  = (blk & 31) << 4;

    const float* Qg = g_Q + (b * NN + i0) * DH;
    #pragma unroll
    for (int idx = t; idx < 1024; idx += 256) Qs[idx] = Qg[idx];
    if (t < 16) mi_s[t] = mask[b * NN + i0 + t];

    // phase-1 mapping
    int jl  = t & 63;
    int ih  = t >> 6;
    // phase-2 mapping
    int ig  = t >> 4;
    int l16 = t & 15;
    // PV mapping: 2-query register tile over a 32-key half
    int d   = t & 15;            // f4 dim
    int tq  = (t >> 4) & 7;      // queries tq and tq+8
    int jq  = t >> 7;            // key half: [jq*32, jq*32+32)

    const float NEGINF = __int_as_float(0xff800000);
    float m_i = NEGINF, l_i = 0.f;
    float4 pa = make_float4(0.f,0.f,0.f,0.f);   // query tq
    float4 pb = make_float4(0.f,0.f,0.f,0.f);   // query tq+8

    const float4* Qs4 = (const float4*)Qs;
    const float4* Ks4 = (const float4*)Ks;
    const float4* Vs4 = (const float4*)Vs;
    float4* Ss4 = (float4*)Ss;

    for (int c = 0; c < 8; c++) {
        int j0 = c * 64;
        __syncthreads();
        const float* Kg = g_K + (b * NN + j0) * DH;
        const float* Vg = g_V + (b * NN + j0) * DH;
        #pragma unroll
        for (int idx = t; idx < 4096; idx += 256) {
            Ks[(idx >> 6) * 68 + (idx & 63)] = Kg[idx];
            Vs[idx] = Vg[idx];
        }
        if (t < 64) mj_s[t] = mask[b * NN + j0 + t];
        __syncthreads();

        // ---- phase 1: scores ----
        float s0 = 0.f, s1 = 0.f, s2 = 0.f, s3 = 0.f;
        #pragma unroll
        for (int k4 = 0; k4 < 16; k4++) {
            float4 kv = Ks4[jl * 17 + k4];
            float4 q;
            q = Qs4[(ih * 4 + 0) * 16 + k4];
            s0 += q.x * kv.x + q.y * kv.y + q.z * kv.z + q.w * kv.w;
            q = Qs4[(ih * 4 + 1) * 16 + k4];
            s1 += q.x * kv.x + q.y * kv.y + q.z * kv.z + q.w * kv.w;
            q = Qs4[(ih * 4 + 2) * 16 + k4];
            s2 += q.x * kv.x + q.y * kv.y + q.z * kv.z + q.w * kv.w;
            q = Qs4[(ih * 4 + 3) * 16 + k4];
            s3 += q.x * kv.x + q.y * kv.y + q.z * kv.z + q.w * kv.w;
        }
        bool mj = (mj_s[jl] != 0);
        Ss[(ih * 4 + 0) * 68 + jl] = mj ? s0 * 0.125f : -1.0e9f;
        Ss[(ih * 4 + 1) * 68 + jl] = mj ? s1 * 0.125f : -1.0e9f;
        Ss[(ih * 4 + 2) * 68 + jl] = mj ? s2 * 0.125f : -1.0e9f;
        Ss[(ih * 4 + 3) * 68 + jl] = mj ? s3 * 0.125f : -1.0e9f;
        __syncthreads();

        // ---- phase 2: online softmax (16-lane groups) ----
        float4 sv = Ss4[ig * 17 + l16];
        float cm = fmaxf(fmaxf(sv.x, sv.y), fmaxf(sv.z, sv.w));
        #pragma unroll
        for (int off = 8; off; off >>= 1)
            cm = fmaxf(cm, __shfl_xor_sync(0xffffffffu, cm, off));
        float m_new = fmaxf(m_i, cm);
        float coef  = __expf(m_i - m_new);
        float4 p;
        p.x = __expf(sv.x - m_new);
        p.y = __expf(sv.y - m_new);
        p.z = __expf(sv.z - m_new);
        p.w = __expf(sv.w - m_new);
        float ps = p.x + p.y + p.z + p.w;
        #pragma unroll
        for (int off = 8; off; off >>= 1)
            ps += __shfl_xor_sync(0xffffffffu, ps, off);
        l_i = l_i * coef + ps;
        m_i = m_new;
        Ss4[ig * 17 + l16] = p;
        if (l16 == 0) coef_s[ig] = coef;
        __syncthreads();            // P + coef visible across warps

        // ---- PV: 2-query tile, V loaded once per key ----
        float cfa = coef_s[tq];
        float cfb = coef_s[tq + 8];
        pa.x *= cfa; pa.y *= cfa; pa.z *= cfa; pa.w *= cfa;
        pb.x *= cfb; pb.y *= cfb; pb.z *= cfb; pb.w *= cfb;
        #pragma unroll 8
        for (int jj = 0; jj < 32; jj++) {
            int j = jq * 32 + jj;
            float4 v  = Vs4[j * 16 + d];
            float p0  = Ss[tq * 68 + j];
            float p1  = Ss[(tq + 8) * 68 + j];
            pa.x += p0 * v.x; pa.y += p0 * v.y; pa.z += p0 * v.z; pa.w += p0 * v.w;
            pb.x += p1 * v.x; pb.y += p1 * v.y; pb.z += p1 * v.z; pb.w += p1 * v.w;
        }
    }

    // ---- final: reduce key-halves, normalize, store ----
    if (l16 == 0) l_s[ig] = l_i;
    __syncthreads();
    float4* red = (float4*)Ks;      // 512 f4 scratch in dead K region
    red[(jq * 16 + tq    ) * 16 + d] = pa;
    red[(jq * 16 + tq + 8) * 16 + d] = pb;
    __syncthreads();

    int q  = t >> 4;
    int dd = t & 15;
    float4 r0 = red[(q     ) * 16 + dd];
    float4 r1 = red[(16 + q) * 16 + dd];
    float inv = mi_s[q] ? (1.f / l_s[q]) : 0.f;
    float4 o;
    o.x = (r0.x + r1.x) * inv;
    o.y = (r0.y + r1.y) * inv;
    o.z = (r0.z + r1.z) * inv;
    o.w = (r0.w + r1.w) * inv;
    ((float4*)outp)[(b * NN + i0 + q) * 16 + dd] = o;

    // replay-safe reset by the last attention block
    __syncthreads();
    if (t == 0) {
        unsigned r = atomicAdd(&g_att_done, 1u);
        if (r == (unsigned)(NBLK_ATT - 1)) {
            atomicExch(&g_qkv_done, 0u);
            atomicExch(&g_att_done, 0u);
        }
    }
}

// ---------------------------------------------------------------------------
extern "C" void kernel_launch(void* const* d_in, const int* in_sizes, int n_in,
                              void* d_out, int out_size)
{
    const float* x    = (const float*)d_in[0];
    const float* e    = (const float*)d_in[1];
    const int*   mask = (const int*)  d_in[2];
    const float* Wq   = (const float*)d_in[3];
    const float* bq   = (const float*)d_in[4];
    const float* Wk   = (const float*)d_in[5];
    const float* bk   = (const float*)d_in[6];
    const float* Wv   = (const float*)d_in[7];
    const float* bv   = (const float*)d_in[8];

    float* outp = (float*)d_out;
    const float4* e4 = (const float4*)e;
    float4* eo4 = (float4*)(outp + OUT_ELEMS);

    fused_kernel<<<GRID, 256>>>(x, mask, Wq, bq, Wk, bk, Wv, bv, e4, eo4, outp);
}

// round 16
// speedup vs baseline: 1.0609x; 1.0609x over previous
#include <cuda_runtime.h>

#define NB 8
#define NN 512
#define DD 256
#define DH 64
#define OUT_ELEMS (NB*NN*DH)            // 262144
#define E4        16777216u             // e element count / 4

// region B: pre-copied by attention blocks before their QKV spin (R13 proven)
#define B_F4      1048576u              // 256 blk * 256 thr * 16 f4  (16 MB)
#define E4A       (E4 - B_F4)           // 15728640
#define SB        65536u                // stride: 256 blk * 256 thr

#define NBLK_QKV 192
#define NBLK_ATT 256
#define NBLK_CPY 1536
#define GRID     (NBLK_QKV + NBLK_ATT + NBLK_CPY)   // 1984
#define CPY_BLKS 1728u                  // copy-capable blocks (QKV + pure)

#define TMA_CHUNK_F4 512u               // 8 KB per bulk chunk
#define TMA_CHUNKS   30720u             // E4A / TMA_CHUNK_F4
#define TMA_BYTES    8192u
#define NBUF         5u                 // 5 x 8KB buffers = 40 KB

__device__ float g_Q[NB*NN*DH];
__device__ float g_K[NB*NN*DH];
__device__ float g_V[NB*NN*DH];
__device__ unsigned g_qkv_done = 0;
__device__ unsigned g_att_done = 0;

// ---------------------------------------------------------------------------
// TMA bulk copy, deep pipeline: 5 buffers, load-ahead 2, thread 0 only.
// Steady state: 3 loads + 2 stores in flight per block.
// ---------------------------------------------------------------------------
__device__ __forceinline__ void tma_expect_load(unsigned mb, unsigned buf,
                                                const void* src)
{
    asm volatile("mbarrier.arrive.expect_tx.shared.b64 _, [%0], %1;"
                 :: "r"(mb), "r"(TMA_BYTES) : "memory");
    asm volatile("cp.async.bulk.shared::cluster.global.mbarrier::complete_tx::bytes "
                 "[%0], [%1], %2, [%3];"
                 :: "r"(buf), "l"(src), "r"(TMA_BYTES), "r"(mb) : "memory");
}

__device__ __forceinline__ void do_copy_tma(int t, unsigned lane,
                                            const float4* __restrict__ e4,
                                            float4* __restrict__ eo4,
                                            void* smbuf)
{
    if (t != 0) return;                 // lone driver thread
    unsigned sb  = (unsigned)__cvta_generic_to_shared(smbuf);
    unsigned mbb = sb + NBUF * TMA_BYTES;
    #pragma unroll
    for (unsigned k = 0; k < NBUF; k++)
        asm volatile("mbarrier.init.shared.b64 [%0], 1;"
                     :: "r"(mbb + 8u*k) : "memory");
    asm volatile("fence.proxy.async.shared::cta;" ::: "memory");

    unsigned ph_bits = 0;               // per-buffer phase parity

    // prologue: loads 0 and 1
    #pragma unroll
    for (unsigned k = 0; k < 2; k++) {
        unsigned ch = lane + k * CPY_BLKS;
        if (ch < TMA_CHUNKS)
            tma_expect_load(mbb + 8u*k, sb + k*TMA_BYTES,
                            (const void*)(e4 + (size_t)ch * TMA_CHUNK_F4));
    }

    #pragma unroll 1
    for (unsigned i = 0; ; i++) {
        unsigned ch = lane + i * CPY_BLKS;
        if (ch >= TMA_CHUNKS) break;

        // issue load(i+2) ahead of waiting on load(i)
        unsigned ch2 = lane + (i + 2u) * CPY_BLKS;
        if (ch2 < TMA_CHUNKS) {
            if (i >= 3)   // buf (i+2)%5 was used by store(i-3); ensure done
                asm volatile("cp.async.bulk.wait_group 2;" ::: "memory");
            unsigned bi2 = (i + 2u) % NBUF;
            tma_expect_load(mbb + 8u*bi2, sb + bi2*TMA_BYTES,
                            (const void*)(e4 + (size_t)ch2 * TMA_CHUNK_F4));
        }

        // wait for load(i) to land (parity)
        unsigned bi = i % NBUF;
        unsigned mb = mbb + 8u*bi;
        unsigned par = (ph_bits >> bi) & 1u;
        unsigned done;
        do {
            asm volatile("{\n\t.reg .pred p;\n\t"
                         "mbarrier.try_wait.parity.shared.b64 p, [%1], %2, 0x989680;\n\t"
                         "selp.b32 %0, 1, 0, p;\n\t}"
                         : "=r"(done) : "r"(mb), "r"(par) : "memory");
        } while (!done);
        ph_bits ^= (1u << bi);

        // store(i)
        void* dst = (void*)(eo4 + (size_t)ch * TMA_CHUNK_F4);
        asm volatile("cp.async.bulk.global.shared::cta.bulk_group [%0], [%1], %2;"
                     :: "l"(dst), "r"(sb + bi*TMA_BYTES), "r"(TMA_BYTES) : "memory");
        asm volatile("cp.async.bulk.commit_group;" ::: "memory");
    }
    asm volatile("cp.async.bulk.wait_group 0;" ::: "memory");
}

__global__ void __launch_bounds__(256, 4) fused_kernel(
    const float* __restrict__ x, const int* __restrict__ mask,
    const float* __restrict__ Wq, const float* __restrict__ bq,
    const float* __restrict__ Wk, const float* __restrict__ bk,
    const float* __restrict__ Wv, const float* __restrict__ bv,
    const float4* __restrict__ e4, float4* __restrict__ eo4,
    float* __restrict__ outp)
{
    __shared__ __align__(128) char sm_raw[42688];
    int t = threadIdx.x;
    unsigned bid = blockIdx.x;

    if (bid < NBLK_QKV) {
        // =================== QKV GEMM role ===================
        float* Xs = (float*)sm_raw;          // 64*65
        float* Ws = Xs + 64*65;              // 64*64

        int which  = bid / 64;               // 0=Q, 1=K, 2=V
        int rowblk = bid % 64;
        const float* W    = (which == 0) ? Wq : (which == 1) ? Wk : Wv;
        const float* bias = (which == 0) ? bq : (which == 1) ? bk : bv;
        float* outw       = (which == 0) ? g_Q : (which == 1) ? g_K : g_V;

        int tx = t & 15;
        int ty = t >> 4;
        int row0 = rowblk * 64;

        float acc[4][4];
        #pragma unroll
        for (int i = 0; i < 4; i++)
            #pragma unroll
            for (int j = 0; j < 4; j++) acc[i][j] = 0.f;

        for (int kt = 0; kt < 4; kt++) {
            int k0 = kt * 64;
            __syncthreads();
            #pragma unroll
            for (int idx = t; idx < 4096; idx += 256) {
                int r  = idx >> 6;
                int kk = idx & 63;
                Xs[r * 65 + kk] = x[(row0 + r) * DD + k0 + kk];
                Ws[idx]         = W[k0 * DH + idx];
            }
            __syncthreads();

            const float4* Ws4 = (const float4*)Ws;
            #pragma unroll 8
            for (int kk = 0; kk < 64; kk++) {
                float4 bv4 = Ws4[kk * 16 + tx];
                #pragma unroll
                for (int i = 0; i < 4; i++) {
                    float a = Xs[(ty * 4 + i) * 65 + kk];
                    acc[i][0] += a * bv4.x;
                    acc[i][1] += a * bv4.y;
                    acc[i][2] += a * bv4.z;
                    acc[i][3] += a * bv4.w;
                }
            }
        }

        #pragma unroll
        for (int i = 0; i < 4; i++) {
            int r = row0 + ty * 4 + i;
            float m = (float)mask[r];
            float4 o;
            o.x = (acc[i][0] + bias[tx * 4 + 0]) * m;
            o.y = (acc[i][1] + bias[tx * 4 + 1]) * m;
            o.z = (acc[i][2] + bias[tx * 4 + 2]) * m;
            o.w = (acc[i][3] + bias[tx * 4 + 3]) * m;
            *(float4*)(outw + r * DH + tx * 4) = o;
        }

        __threadfence();
        __syncthreads();                 // all warps done with Xs/Ws before t0 reuses smem
        if (t == 0) atomicAdd(&g_qkv_done, 1u);

        do_copy_tma(t, bid, e4, eo4, sm_raw);
        return;
    }

    if (bid >= NBLK_QKV + NBLK_ATT) {
        // =================== pure copy role ===================
        do_copy_tma(t, bid - NBLK_ATT, e4, eo4, sm_raw);
        return;
    }

    // =================== attention role ===================
    // Pre-copy region B while the QKV GEMMs run (R13 proven).
    {
        unsigned cid = bid - NBLK_QKV;
        unsigned g = E4A + cid * 256u + (unsigned)t;
        #pragma unroll 1
        for (int it = 0; it < 4; it++) {
            unsigned i = g + (unsigned)it * 4u * SB;
            float4 a = __ldcs(e4 + i);
            float4 b = __ldcs(e4 + i + SB);
            float4 c = __ldcs(e4 + i + 2u*SB);
            float4 d = __ldcs(e4 + i + 3u*SB);
            __stcs(eo4 + i,         a);
            __stcs(eo4 + i + SB,    b);
            __stcs(eo4 + i + 2u*SB, c);
            __stcs(eo4 + i + 3u*SB, d);
        }
    }

    if (t == 0) {
        while (atomicAdd(&g_qkv_done, 0u) < (unsigned)NBLK_QKV)
            __nanosleep(64);
    }
    __syncthreads();
    __threadfence();

    float* Qs     = (float*)sm_raw;      // 16*64 = 1024
    float* Ks     = Qs + 1024;           // 64*68 = 4352 (later: reduction scratch)
    float* Vs     = Ks + 4352;           // 64*64 = 4096
    float* Ss     = Vs + 4096;           // 16*68 = 1088 (P, padded stride 68)
    float* coef_s = Ss + 1088;           // 16
    float* l_s    = coef_s + 16;         // 16
    int*   mj_s   = (int*)(l_s + 16);    // 64
    int*   mi_s   = mj_s + 64;           // 16

    int blk = bid - NBLK_QKV;
    int b   = blk >> 5;
    int i0  = (blk & 31) << 4;

    const float* Qg = g_Q + (b * NN + i0) * DH;
    #pragma unroll
    for (int idx = t; idx < 1024; idx += 256) Qs[idx] = Qg[idx];
    if (t < 16) mi_s[t] = mask[b * NN + i0 + t];

    // phase-1 mapping
    int jl  = t & 63;
    int ih  = t >> 6;
    // phase-2 mapping
    int ig  = t >> 4;
    int l16 = t & 15;
    // PV mapping: 2-query register tile over a 32-key half
    int d   = t & 15;            // f4 dim
    int tq  = (t >> 4) & 7;      // queries tq and tq+8
    int jq  = t >> 7;            // key half: [jq*32, jq*32+32)

    const float NEGINF = __int_as_float(0xff800000);
    float m_i = NEGINF, l_i = 0.f;
    float4 pa = make_float4(0.f,0.f,0.f,0.f);   // query tq
    float4 pb = make_float4(0.f,0.f,0.f,0.f);   // query tq+8

    const float4* Qs4 = (const float4*)Qs;
    const float4* Ks4 = (const float4*)Ks;
    const float4* Vs4 = (const float4*)Vs;
    float4* Ss4 = (float4*)Ss;

    for (int c = 0; c < 8; c++) {
        int j0 = c * 64;
        __syncthreads();
        const float* Kg = g_K + (b * NN + j0) * DH;
        const float* Vg = g_V + (b * NN + j0) * DH;
        #pragma unroll
        for (int idx = t; idx < 4096; idx += 256) {
            Ks[(idx >> 6) * 68 + (idx & 63)] = Kg[idx];
            Vs[idx] = Vg[idx];
        }
        if (t < 64) mj_s[t] = mask[b * NN + j0 + t];
        __syncthreads();

        // ---- phase 1: scores ----
        float s0 = 0.f, s1 = 0.f, s2 = 0.f, s3 = 0.f;
        #pragma unroll
        for (int k4 = 0; k4 < 16; k4++) {
            float4 kv = Ks4[jl * 17 + k4];
            float4 q;
            q = Qs4[(ih * 4 + 0) * 16 + k4];
            s0 += q.x * kv.x + q.y * kv.y + q.z * kv.z + q.w * kv.w;
            q = Qs4[(ih * 4 + 1) * 16 + k4];
            s1 += q.x * kv.x + q.y * kv.y + q.z * kv.z + q.w * kv.w;
            q = Qs4[(ih * 4 + 2) * 16 + k4];
            s2 += q.x * kv.x + q.y * kv.y + q.z * kv.z + q.w * kv.w;
            q = Qs4[(ih * 4 + 3) * 16 + k4];
            s3 += q.x * kv.x + q.y * kv.y + q.z * kv.z + q.w * kv.w;
        }
        bool mj = (mj_s[jl] != 0);
        Ss[(ih * 4 + 0) * 68 + jl] = mj ? s0 * 0.125f : -1.0e9f;
        Ss[(ih * 4 + 1) * 68 + jl] = mj ? s1 * 0.125f : -1.0e9f;
        Ss[(ih * 4 + 2) * 68 + jl] = mj ? s2 * 0.125f : -1.0e9f;
        Ss[(ih * 4 + 3) * 68 + jl] = mj ? s3 * 0.125f : -1.0e9f;
        __syncthreads();

        // ---- phase 2: online softmax (16-lane groups) ----
        float4 sv = Ss4[ig * 17 + l16];
        float cm = fmaxf(fmaxf(sv.x, sv.y), fmaxf(sv.z, sv.w));
        #pragma unroll
        for (int off = 8; off; off >>= 1)
            cm = fmaxf(cm, __shfl_xor_sync(0xffffffffu, cm, off));
        float m_new = fmaxf(m_i, cm);
        float coef  = __expf(m_i - m_new);
        float4 p;
        p.x = __expf(sv.x - m_new);
        p.y = __expf(sv.y - m_new);
        p.z = __expf(sv.z - m_new);
        p.w = __expf(sv.w - m_new);
        float ps = p.x + p.y + p.z + p.w;
        #pragma unroll
        for (int off = 8; off; off >>= 1)
            ps += __shfl_xor_sync(0xffffffffu, ps, off);
        l_i = l_i * coef + ps;
        m_i = m_new;
        Ss4[ig * 17 + l16] = p;
        if (l16 == 0) coef_s[ig] = coef;
        __syncthreads();            // P + coef visible across warps

        // ---- PV: 2-query tile, V loaded once per key ----
        float cfa = coef_s[tq];
        float cfb = coef_s[tq + 8];
        pa.x *= cfa; pa.y *= cfa; pa.z *= cfa; pa.w *= cfa;
        pb.x *= cfb; pb.y *= cfb; pb.z *= cfb; pb.w *= cfb;
        #pragma unroll 8
        for (int jj = 0; jj < 32; jj++) {
            int j = jq * 32 + jj;
            float4 v  = Vs4[j * 16 + d];
            float p0  = Ss[tq * 68 + j];
            float p1  = Ss[(tq + 8) * 68 + j];
            pa.x += p0 * v.x; pa.y += p0 * v.y; pa.z += p0 * v.z; pa.w += p0 * v.w;
            pb.x += p1 * v.x; pb.y += p1 * v.y; pb.z += p1 * v.z; pb.w += p1 * v.w;
        }
    }

    // ---- final: reduce key-halves, normalize, store ----
    if (l16 == 0) l_s[ig] = l_i;
    __syncthreads();
    float4* red = (float4*)Ks;      // 512 f4 scratch in dead K region
    red[(jq * 16 + tq    ) * 16 + d] = pa;
    red[(jq * 16 + tq + 8) * 16 + d] = pb;
    __syncthreads();

    int q  = t >> 4;
    int dd = t & 15;
    float4 r0 = red[(q     ) * 16 + dd];
    float4 r1 = red[(16 + q) * 16 + dd];
    float inv = mi_s[q] ? (1.f / l_s[q]) : 0.f;
    float4 o;
    o.x = (r0.x + r1.x) * inv;
    o.y = (r0.y + r1.y) * inv;
    o.z = (r0.z + r1.z) * inv;
    o.w = (r0.w + r1.w) * inv;
    ((float4*)outp)[(b * NN + i0 + q) * 16 + dd] = o;

    // replay-safe reset by the last attention block
    __syncthreads();
    if (t == 0) {
        unsigned r = atomicAdd(&g_att_done, 1u);
        if (r == (unsigned)(NBLK_ATT - 1)) {
            atomicExch(&g_qkv_done, 0u);
            atomicExch(&g_att_done, 0u);
        }
    }
}

// ---------------------------------------------------------------------------
extern "C" void kernel_launch(void* const* d_in, const int* in_sizes, int n_in,
                              void* d_out, int out_size)
{
    const float* x    = (const float*)d_in[0];
    const float* e    = (const float*)d_in[1];
    const int*   mask = (const int*)  d_in[2];
    const float* Wq   = (const float*)d_in[3];
    const float* bq   = (const float*)d_in[4];
    const float* Wk   = (const float*)d_in[5];
    const float* bk   = (const float*)d_in[6];
    const float* Wv   = (const float*)d_in[7];
    const float* bv   = (const float*)d_in[8];

    float* outp = (float*)d_out;
    const float4* e4 = (const float4*)e;
    float4* eo4 = (float4*)(outp + OUT_ELEMS);

    fused_kernel<<<GRID, 256>>>(x, mask, Wq, bq, Wk, bk, Wv, bv, e4, eo4, outp);
}